// round 3
// baseline (speedup 1.0000x reference)
#include <cuda_runtime.h>

#define Nn 100000
#define Hh 96

// ---------------- static device scratch (no allocations allowed) ----------------
__device__ __align__(16) float g_accum[3*Nn*Hh + 3*Nn];  // agg0,agg1,agg2 then den0,den1,den2
__device__ __align__(16) float g_A[4*Nn];                // aS0, aD0, aS1, aD1
__device__ __align__(16) float g_Mbig[384*Hh];           // rows 0-95: M0, then M1_t (t=0..2)
__device__ __align__(16) float g_D[3][Hh*Hh];            // WmDst_t @ Wu_t
__device__ __align__(16) float g_V[4*Hh];                // attention vectors
__device__ __align__(16) float g_ct[3][Hh];              // ef@WmEf + bm
__device__ __align__(16) float g_cw[3][Hh];              // c_t @ Wu_t
__device__ __align__(16) float g_bu2[Hh];                // bu + sum cw
__device__ __align__(16) float g_rden[3*Nn];
__device__ int g_defList[Nn];
__device__ int g_defCount;

// ---------------- zero accumulators ----------------
__global__ void k_zero() {
    const int n4 = (3*Nn*Hh + 3*Nn) / 4;
    float4 z = make_float4(0.f, 0.f, 0.f, 0.f);
    float4* p = reinterpret_cast<float4*>(g_accum);
    for (int i = blockIdx.x*blockDim.x + threadIdx.x; i < n4; i += gridDim.x*blockDim.x)
        p[i] = z;
    if (blockIdx.x == 0 && threadIdx.x == 0) g_defCount = 0;
}

// ---------------- small prep: V vectors, c_t, cw_t, bu2 ----------------
__global__ void k_prep_small(
    const float* __restrict__ Wn0, const float* __restrict__ Wa0,
    const float* __restrict__ Wn1, const float* __restrict__ Wa1,
    const float* __restrict__ Wm0, const float* __restrict__ bm0, const float* __restrict__ ef0,
    const float* __restrict__ Wm1, const float* __restrict__ bm1, const float* __restrict__ ef1,
    const float* __restrict__ Wm2, const float* __restrict__ bm2, const float* __restrict__ ef2,
    const float* __restrict__ Wu, const float* __restrict__ bu)
{
    int i = threadIdx.x;
    if (i < Hh) {
        float s0 = 0.f, d0 = 0.f, s1 = 0.f, d1 = 0.f;
        for (int j = 0; j < 32; j++) {
            float w0 = Wn0[i*32+j], w1 = Wn1[i*32+j];
            s0 += w0*Wa0[j];     d0 += w0*Wa0[32+j];
            s1 += w1*Wa1[j];     d1 += w1*Wa1[32+j];
        }
        g_V[0*Hh+i] = s0; g_V[1*Hh+i] = d0; g_V[2*Hh+i] = s1; g_V[3*Hh+i] = d1;

        const float* Wms[3] = {Wm0, Wm1, Wm2};
        const float* bms[3] = {bm0, bm1, bm2};
        const float* efs[3] = {ef0, ef1, ef2};
        for (int t = 0; t < 3; t++) {
            float c = bms[t][i];
            for (int d = 0; d < 16; d++) c += efs[t][d] * Wms[t][(192+d)*Hh + i];
            g_ct[t][i] = c;
        }
    }
    __syncthreads();
    if (i < Hh) {
        float b = bu[i];
        for (int t = 0; t < 3; t++) {
            float cw = 0.f;
            for (int c = 0; c < Hh; c++) cw += g_ct[t][c] * Wu[(Hh + t*Hh + c)*Hh + i];
            g_cw[t][i] = cw;
            b += cw;
        }
        g_bu2[i] = b;
    }
}

// ---------------- prep: M1_t = WmSrc_t@Wu_t (into Mbig rows 96..383), D_t = WmDst_t@Wu_t ----------------
__global__ void k_prep_mats(const float* __restrict__ Wm0, const float* __restrict__ Wm1,
                            const float* __restrict__ Wm2, const float* __restrict__ Wu)
{
    int idx = blockIdx.x*blockDim.x + threadIdx.x;
    if (idx >= 3*Hh*Hh) return;
    int t = idx / (Hh*Hh);
    int r = idx % (Hh*Hh);
    int k = r / Hh, j = r % Hh;
    const float* Wm = (t == 0) ? Wm0 : ((t == 1) ? Wm1 : Wm2);
    float m1 = 0.f, dd = 0.f;
    const float* wuBase = Wu + (Hh + t*Hh)*Hh + j;
    for (int c = 0; c < Hh; c++) {
        float wu = wuBase[c*Hh];
        m1 += Wm[k*Hh + c] * wu;
        dd += Wm[(Hh + k)*Hh + c] * wu;
    }
    g_Mbig[(Hh + t*Hh + k)*Hh + j] = m1;
    g_D[t][k*Hh + j] = dd;
}

__global__ void k_prep_m0(const float* __restrict__ Wu) {
    int idx = blockIdx.x*blockDim.x + threadIdx.x;
    if (idx >= Hh*Hh) return;
    g_Mbig[idx] = Wu[idx] + g_D[0][idx] + g_D[1][idx] + g_D[2][idx];
}

// ---------------- per-node attention scalars: a = h . V ----------------
// 8 lanes per node, 4 nodes per warp. Grid must supply >= Nn/4 warps.
__global__ void k_anode(const float* __restrict__ h) {
    __shared__ float sv[4*Hh];
    for (int i = threadIdx.x; i < 4*Hh; i += blockDim.x) sv[i] = g_V[i];
    __syncthreads();
    int gtid = blockIdx.x*blockDim.x + threadIdx.x;
    int lane = gtid & 31;
    int k = lane & 7;
    int n = (gtid >> 5)*4 + (lane >> 3);
    if (n >= Nn) return;
    const float4* hp = reinterpret_cast<const float4*>(h + (size_t)n*Hh);
    float a0 = 0.f, a1 = 0.f, a2 = 0.f, a3 = 0.f;
    #pragma unroll
    for (int j = 0; j < 3; j++) {
        int idx = k + j*8;
        float4 hv = hp[idx];
        const float* v0 = sv + 0*Hh + idx*4;
        const float* v1 = sv + 1*Hh + idx*4;
        const float* v2 = sv + 2*Hh + idx*4;
        const float* v3 = sv + 3*Hh + idx*4;
        a0 += hv.x*v0[0] + hv.y*v0[1] + hv.z*v0[2] + hv.w*v0[3];
        a1 += hv.x*v1[0] + hv.y*v1[1] + hv.z*v1[2] + hv.w*v1[3];
        a2 += hv.x*v2[0] + hv.y*v2[1] + hv.z*v2[2] + hv.w*v2[3];
        a3 += hv.x*v3[0] + hv.y*v3[1] + hv.z*v3[2] + hv.w*v3[3];
    }
    #pragma unroll
    for (int off = 4; off > 0; off >>= 1) {
        a0 += __shfl_xor_sync(0xffffffffu, a0, off);
        a1 += __shfl_xor_sync(0xffffffffu, a1, off);
        a2 += __shfl_xor_sync(0xffffffffu, a2, off);
        a3 += __shfl_xor_sync(0xffffffffu, a3, off);
    }
    if (k == 0) {
        g_A[0*Nn + n] = a0; g_A[1*Nn + n] = a1;
        g_A[2*Nn + n] = a2; g_A[3*Nn + n] = a3;
    }
}

// ---------------- edge pass: agg[dst] += w * h[src], den[dst] += w ----------------
// 8 lanes per edge (3 float4 each), 4 edges per warp, v4 reductions to L2.
template<int ATTN>
__global__ void k_edge(const int* __restrict__ src, const int* __restrict__ dst,
                       const float* __restrict__ h, int E_, int t)
{
    int gtid = blockIdx.x*blockDim.x + threadIdx.x;
    int lane = gtid & 31;
    int k = lane & 7;
    int e = (gtid >> 5)*4 + (lane >> 3);
    if (e >= E_) return;
    int s = src[e], d = dst[e];
    float w = 1.f;
    if (ATTN) {
        const float* aS = g_A + (2*t)*Nn;
        const float* aD = g_A + (2*t + 1)*Nn;
        float sc = aS[s] + aD[d];
        sc = sc > 0.f ? sc : 0.01f*sc;   // leaky_relu
        w = __expf(sc);                  // max-free softmax (scores bounded, no overflow)
    }
    if (k == 0) atomicAdd(g_accum + 3*Nn*Hh + t*Nn + d, w);
    const float4* hp = reinterpret_cast<const float4*>(h + (size_t)s*Hh);
    float* ag = g_accum + (size_t)t*Nn*Hh + (size_t)d*Hh;
    #pragma unroll
    for (int j = 0; j < 3; j++) {
        int idx = k + j*8;
        float4 v = hp[idx];
        if (ATTN) { v.x *= w; v.y *= w; v.z *= w; v.w *= w; }
        asm volatile("red.global.add.v4.f32 [%0], {%1,%2,%3,%4};"
                     :: "l"(ag + idx*4), "f"(v.x), "f"(v.y), "f"(v.z), "f"(v.w)
                     : "memory");
    }
}

// ---------------- scan: reciprocal denominators + deficient-node list ----------------
__global__ void k_scan() {
    int n = blockIdx.x*blockDim.x + threadIdx.x;
    if (n >= Nn) return;
    bool bad = false;
    #pragma unroll
    for (int t = 0; t < 3; t++) {
        float dn = g_accum[3*Nn*Hh + t*Nn + n];
        bool ok = dn > 0.f;
        g_rden[t*Nn + n] = ok ? 1.f/dn : 0.f;
        bad |= !ok;
    }
    if (bad) {
        int p = atomicAdd(&g_defCount, 1);
        g_defList[p] = n;
    }
}

// ---------------- combine GEMM: out = relu([h | G0 | G1 | G2] @ Mbig + bu2) ----------------
// Tile 128 rows x 96 cols, K=384 in chunks of 32, thread tile 8x6.
__global__ void __launch_bounds__(256) k_combine(const float* __restrict__ h,
                                                 float* __restrict__ out)
{
    __shared__ float As[32][132];   // transposed [k][row], padded
    __shared__ float Bs[32][96];
    __shared__ float Ss[3][128];
    int tid = threadIdx.x;
    int row0 = blockIdx.x * 128;

    for (int i = tid; i < 3*128; i += 256) {
        int t = i >> 7, r = i & 127;
        int n = row0 + r;
        Ss[t][r] = (n < Nn) ? g_rden[t*Nn + n] : 0.f;
    }
    __syncthreads();

    float acc[8][6];
    #pragma unroll
    for (int i = 0; i < 8; i++)
        #pragma unroll
        for (int j = 0; j < 6; j++) acc[i][j] = 0.f;

    int rowg = tid >> 4, colg = tid & 15;

    for (int kc = 0; kc < 12; kc++) {
        int seg = kc / 3;            // 0: h, 1..3: agg_t
        int kin = (kc % 3) * 32;
        const float* Asrc = (seg == 0) ? h : (g_accum + (size_t)(seg - 1)*Nn*Hh);
        #pragma unroll
        for (int p = 0; p < 4; p++) {
            int r = (tid >> 3) + 32*p;
            int c4 = tid & 7;
            int n = row0 + r;
            float4 v = make_float4(0.f, 0.f, 0.f, 0.f);
            if (n < Nn) v = *reinterpret_cast<const float4*>(Asrc + (size_t)n*Hh + kin + c4*4);
            float sc = (seg == 0) ? 1.f : Ss[seg-1][r];
            As[c4*4+0][r] = v.x*sc;
            As[c4*4+1][r] = v.y*sc;
            As[c4*4+2][r] = v.z*sc;
            As[c4*4+3][r] = v.w*sc;
        }
        #pragma unroll
        for (int p = 0; p < 3; p++) {
            int i4 = tid + p*256;          // 0..767
            int kk = i4 / 24, j4 = i4 % 24;
            *reinterpret_cast<float4*>(&Bs[kk][j4*4]) =
                *reinterpret_cast<const float4*>(g_Mbig + (seg*96 + kin + kk)*96 + j4*4);
        }
        __syncthreads();
        #pragma unroll
        for (int k = 0; k < 32; k++) {
            float4 a0 = *reinterpret_cast<const float4*>(&As[k][rowg*8]);
            float4 a1 = *reinterpret_cast<const float4*>(&As[k][rowg*8+4]);
            float2 b0 = *reinterpret_cast<const float2*>(&Bs[k][colg*6]);
            float2 b1 = *reinterpret_cast<const float2*>(&Bs[k][colg*6+2]);
            float2 b2 = *reinterpret_cast<const float2*>(&Bs[k][colg*6+4]);
            float a[8] = {a0.x, a0.y, a0.z, a0.w, a1.x, a1.y, a1.z, a1.w};
            float b[6] = {b0.x, b0.y, b1.x, b1.y, b2.x, b2.y};
            #pragma unroll
            for (int i = 0; i < 8; i++)
                #pragma unroll
                for (int j = 0; j < 6; j++)
                    acc[i][j] += a[i]*b[j];
        }
        __syncthreads();
    }

    #pragma unroll
    for (int i = 0; i < 8; i++) {
        int n = row0 + rowg*8 + i;
        if (n < Nn) {
            #pragma unroll
            for (int j = 0; j < 6; j++) {
                int c = colg*6 + j;
                out[(size_t)n*Hh + c] = fmaxf(acc[i][j] + g_bu2[c], 0.f);
            }
        }
    }
}

// ---------------- fixup for nodes with a zero-degree edge type ----------------
__global__ void k_fixup(const float* __restrict__ h, const float* __restrict__ bu,
                        float* __restrict__ out)
{
    int cnt = g_defCount;
    int j = threadIdx.x;   // 96 threads
    for (int i = blockIdx.x; i < cnt; i += gridDim.x) {
        int n = g_defList[i];
        float ok[3];
        #pragma unroll
        for (int t = 0; t < 3; t++)
            ok[t] = (g_accum[3*Nn*Hh + t*Nn + n] > 0.f) ? 1.f : 0.f;
        float y = bu[j];
        #pragma unroll
        for (int t = 0; t < 3; t++) y += ok[t]*g_cw[t][j];
        const float* hn = h + (size_t)n*Hh;
        for (int kk = 0; kk < Hh; kk++) {
            float m = g_Mbig[kk*Hh + j];
            #pragma unroll
            for (int t = 0; t < 3; t++)
                if (ok[t] == 0.f) m -= g_D[t][kk*Hh + j];
            y += hn[kk]*m;
        }
        #pragma unroll
        for (int t = 0; t < 3; t++) {
            if (ok[t] != 0.f) {
                float rd = g_rden[t*Nn + n];
                const float* agg = g_accum + (size_t)t*Nn*Hh + (size_t)n*Hh;
                for (int kk = 0; kk < Hh; kk++)
                    y += agg[kk]*rd*g_Mbig[(Hh + t*Hh + kk)*Hh + j];
            }
        }
        out[(size_t)n*Hh + j] = fmaxf(y, 0.f);
    }
}

// ---------------- launch ----------------
extern "C" void kernel_launch(void* const* d_in, const int* in_sizes, int n_in,
                              void* d_out, int out_size)
{
    const float* h    = (const float*)d_in[0];
    const int*   src0 = (const int*)d_in[1];
    const int*   dst0 = (const int*)d_in[2];
    const int*   src1 = (const int*)d_in[3];
    const int*   dst1 = (const int*)d_in[4];
    const int*   src2 = (const int*)d_in[5];
    const int*   dst2 = (const int*)d_in[6];
    const float* Wm0 = (const float*)d_in[7];
    const float* bm0 = (const float*)d_in[8];
    const float* ef0 = (const float*)d_in[9];
    const float* Wm1 = (const float*)d_in[10];
    const float* bm1 = (const float*)d_in[11];
    const float* ef1 = (const float*)d_in[12];
    const float* Wm2 = (const float*)d_in[13];
    const float* bm2 = (const float*)d_in[14];
    const float* ef2 = (const float*)d_in[15];
    const float* Wn0 = (const float*)d_in[16];
    const float* Wa0 = (const float*)d_in[17];
    const float* Wn1 = (const float*)d_in[18];
    const float* Wa1 = (const float*)d_in[19];
    const float* Wu  = (const float*)d_in[20];
    const float* bu  = (const float*)d_in[21];
    float* out = (float*)d_out;

    int E0 = in_sizes[1], E1 = in_sizes[3], E2 = in_sizes[5];

    // k_anode: 4 nodes/warp -> need ceil(Nn/4) warps -> ceil(Nn/4*32/256) blocks
    int anode_blocks = ((Nn + 3)/4*32 + 255)/256;

    k_zero<<<2048, 256>>>();
    k_prep_small<<<1, 96>>>(Wn0, Wa0, Wn1, Wa1,
                            Wm0, bm0, ef0, Wm1, bm1, ef1, Wm2, bm2, ef2, Wu, bu);
    k_prep_mats<<<(3*96*96 + 255)/256, 256>>>(Wm0, Wm1, Wm2, Wu);
    k_prep_m0<<<(96*96 + 255)/256, 256>>>(Wu);
    k_anode<<<anode_blocks, 256>>>(h);
    k_edge<1><<<(E0 + 31)/32, 256>>>(src0, dst0, h, E0, 0);
    k_edge<1><<<(E1 + 31)/32, 256>>>(src1, dst1, h, E1, 1);
    k_edge<0><<<(E2 + 31)/32, 256>>>(src2, dst2, h, E2, 2);
    k_scan<<<(Nn + 255)/256, 256>>>();
    k_combine<<<(Nn + 127)/128, 256>>>(h, out);
    k_fixup<<<1024, 96>>>(h, bu, out);
}

// round 4
// speedup vs baseline: 1.0428x; 1.0428x over previous
#include <cuda_runtime.h>

#define Nn 100000
#define Hh 96

typedef unsigned long long u64;

// ---------------- static device scratch (no allocations allowed) ----------------
__device__ __align__(16) float g_accum[3*Nn*Hh + 3*Nn];  // agg0,agg1,agg2 then den0,den1,den2
__device__ __align__(16) float g_A[4*Nn];                // aS0, aD0, aS1, aD1
__device__ __align__(16) float g_Mbig[384*Hh];           // rows 0-95: M0, then M1_t (t=0..2)
__device__ __align__(16) float g_D[3][Hh*Hh];            // WmDst_t @ Wu_t
__device__ __align__(16) float g_V[4*Hh];                // attention vectors
__device__ __align__(16) float g_ct[3][Hh];              // ef@WmEf + bm
__device__ __align__(16) float g_cw[3][Hh];              // c_t @ Wu_t
__device__ __align__(16) float g_bu2[Hh];                // bu + sum cw
__device__ __align__(16) float g_rden[3*Nn];
__device__ int g_defList[Nn];
__device__ int g_defCount;

// ---------------- zero accumulators ----------------
__global__ void k_zero() {
    const int n4 = (3*Nn*Hh + 3*Nn) / 4;
    float4 z = make_float4(0.f, 0.f, 0.f, 0.f);
    float4* p = reinterpret_cast<float4*>(g_accum);
    for (int i = blockIdx.x*blockDim.x + threadIdx.x; i < n4; i += gridDim.x*blockDim.x)
        p[i] = z;
    if (blockIdx.x == 0 && threadIdx.x == 0) g_defCount = 0;
}

// ---------------- small prep: V vectors, c_t, cw_t, bu2 ----------------
__global__ void k_prep_small(
    const float* __restrict__ Wn0, const float* __restrict__ Wa0,
    const float* __restrict__ Wn1, const float* __restrict__ Wa1,
    const float* __restrict__ Wm0, const float* __restrict__ bm0, const float* __restrict__ ef0,
    const float* __restrict__ Wm1, const float* __restrict__ bm1, const float* __restrict__ ef1,
    const float* __restrict__ Wm2, const float* __restrict__ bm2, const float* __restrict__ ef2,
    const float* __restrict__ Wu, const float* __restrict__ bu)
{
    int i = threadIdx.x;
    if (i < Hh) {
        float s0 = 0.f, d0 = 0.f, s1 = 0.f, d1 = 0.f;
        for (int j = 0; j < 32; j++) {
            float w0 = Wn0[i*32+j], w1 = Wn1[i*32+j];
            s0 += w0*Wa0[j];     d0 += w0*Wa0[32+j];
            s1 += w1*Wa1[j];     d1 += w1*Wa1[32+j];
        }
        g_V[0*Hh+i] = s0; g_V[1*Hh+i] = d0; g_V[2*Hh+i] = s1; g_V[3*Hh+i] = d1;

        const float* Wms[3] = {Wm0, Wm1, Wm2};
        const float* bms[3] = {bm0, bm1, bm2};
        const float* efs[3] = {ef0, ef1, ef2};
        for (int t = 0; t < 3; t++) {
            float c = bms[t][i];
            for (int d = 0; d < 16; d++) c += efs[t][d] * Wms[t][(192+d)*Hh + i];
            g_ct[t][i] = c;
        }
    }
    __syncthreads();
    if (i < Hh) {
        float b = bu[i];
        for (int t = 0; t < 3; t++) {
            float cw = 0.f;
            for (int c = 0; c < Hh; c++) cw += g_ct[t][c] * Wu[(Hh + t*Hh + c)*Hh + i];
            g_cw[t][i] = cw;
            b += cw;
        }
        g_bu2[i] = b;
    }
}

// ---------------- prep: M1_t = WmSrc_t@Wu_t (into Mbig rows 96..383), D_t = WmDst_t@Wu_t ----------------
__global__ void k_prep_mats(const float* __restrict__ Wm0, const float* __restrict__ Wm1,
                            const float* __restrict__ Wm2, const float* __restrict__ Wu)
{
    int idx = blockIdx.x*blockDim.x + threadIdx.x;
    if (idx >= 3*Hh*Hh) return;
    int t = idx / (Hh*Hh);
    int r = idx % (Hh*Hh);
    int k = r / Hh, j = r % Hh;
    const float* Wm = (t == 0) ? Wm0 : ((t == 1) ? Wm1 : Wm2);
    float m1 = 0.f, dd = 0.f;
    const float* wuBase = Wu + (Hh + t*Hh)*Hh + j;
    for (int c = 0; c < Hh; c++) {
        float wu = wuBase[c*Hh];
        m1 += Wm[k*Hh + c] * wu;
        dd += Wm[(Hh + k)*Hh + c] * wu;
    }
    g_Mbig[(Hh + t*Hh + k)*Hh + j] = m1;
    g_D[t][k*Hh + j] = dd;
}

__global__ void k_prep_m0(const float* __restrict__ Wu) {
    int idx = blockIdx.x*blockDim.x + threadIdx.x;
    if (idx >= Hh*Hh) return;
    g_Mbig[idx] = Wu[idx] + g_D[0][idx] + g_D[1][idx] + g_D[2][idx];
}

// ---------------- per-node attention scalars: a = h . V ----------------
// 8 lanes per node, 4 nodes per warp. Grid must supply >= Nn/4 warps.
__global__ void k_anode(const float* __restrict__ h) {
    __shared__ float sv[4*Hh];
    for (int i = threadIdx.x; i < 4*Hh; i += blockDim.x) sv[i] = g_V[i];
    __syncthreads();
    int gtid = blockIdx.x*blockDim.x + threadIdx.x;
    int lane = gtid & 31;
    int k = lane & 7;
    int n = (gtid >> 5)*4 + (lane >> 3);
    if (n >= Nn) return;
    const float4* hp = reinterpret_cast<const float4*>(h + (size_t)n*Hh);
    float a0 = 0.f, a1 = 0.f, a2 = 0.f, a3 = 0.f;
    #pragma unroll
    for (int j = 0; j < 3; j++) {
        int idx = k + j*8;
        float4 hv = hp[idx];
        const float* v0 = sv + 0*Hh + idx*4;
        const float* v1 = sv + 1*Hh + idx*4;
        const float* v2 = sv + 2*Hh + idx*4;
        const float* v3 = sv + 3*Hh + idx*4;
        a0 += hv.x*v0[0] + hv.y*v0[1] + hv.z*v0[2] + hv.w*v0[3];
        a1 += hv.x*v1[0] + hv.y*v1[1] + hv.z*v1[2] + hv.w*v1[3];
        a2 += hv.x*v2[0] + hv.y*v2[1] + hv.z*v2[2] + hv.w*v2[3];
        a3 += hv.x*v3[0] + hv.y*v3[1] + hv.z*v3[2] + hv.w*v3[3];
    }
    #pragma unroll
    for (int off = 4; off > 0; off >>= 1) {
        a0 += __shfl_xor_sync(0xffffffffu, a0, off);
        a1 += __shfl_xor_sync(0xffffffffu, a1, off);
        a2 += __shfl_xor_sync(0xffffffffu, a2, off);
        a3 += __shfl_xor_sync(0xffffffffu, a3, off);
    }
    if (k == 0) {
        g_A[0*Nn + n] = a0; g_A[1*Nn + n] = a1;
        g_A[2*Nn + n] = a2; g_A[3*Nn + n] = a3;
    }
}

// ---------------- merged edge pass over all 3 types ----------------
// 8 lanes per edge (3 float4 each), 4 edges per warp, v4 reductions to L2.
__global__ void k_edge_all(const int* __restrict__ s0, const int* __restrict__ d0,
                           const int* __restrict__ s1, const int* __restrict__ d1,
                           const int* __restrict__ s2, const int* __restrict__ d2,
                           const float* __restrict__ h, int E0, int E1, int E2)
{
    int W0 = (E0 + 3) >> 2, W1 = (E1 + 3) >> 2, W2 = (E2 + 3) >> 2;
    int gtid = blockIdx.x*blockDim.x + threadIdx.x;
    int w = gtid >> 5;
    int lane = gtid & 31;
    int t, wl, Ew;
    const int *sp, *dp;
    if (w < W0)            { t = 0; wl = w;          Ew = E0; sp = s0; dp = d0; }
    else if (w < W0 + W1)  { t = 1; wl = w - W0;     Ew = E1; sp = s1; dp = d1; }
    else if (w < W0+W1+W2) { t = 2; wl = w - W0 - W1; Ew = E2; sp = s2; dp = d2; }
    else return;

    int k = lane & 7;
    int e = wl*4 + (lane >> 3);
    if (e >= Ew) return;
    int s = sp[e], d = dp[e];
    float w8 = 1.f;
    if (t < 2) {
        float sc = g_A[(2*t)*Nn + s] + g_A[(2*t + 1)*Nn + d];
        sc = sc > 0.f ? sc : 0.01f*sc;   // leaky_relu
        w8 = __expf(sc);                 // max-free softmax (scores bounded, no overflow)
    }
    if (k == 0) atomicAdd(g_accum + 3*Nn*Hh + t*Nn + d, w8);
    const float4* hp = reinterpret_cast<const float4*>(h + (size_t)s*Hh);
    float* ag = g_accum + (size_t)t*Nn*Hh + (size_t)d*Hh;
    #pragma unroll
    for (int j = 0; j < 3; j++) {
        int idx = k + j*8;
        float4 v = hp[idx];
        if (t < 2) { v.x *= w8; v.y *= w8; v.z *= w8; v.w *= w8; }
        asm volatile("red.global.add.v4.f32 [%0], {%1,%2,%3,%4};"
                     :: "l"(ag + idx*4), "f"(v.x), "f"(v.y), "f"(v.z), "f"(v.w)
                     : "memory");
    }
}

// ---------------- scan: reciprocal denominators + deficient-node list ----------------
__global__ void k_scan() {
    int n = blockIdx.x*blockDim.x + threadIdx.x;
    if (n >= Nn) return;
    bool bad = false;
    #pragma unroll
    for (int t = 0; t < 3; t++) {
        float dn = g_accum[3*Nn*Hh + t*Nn + n];
        bool ok = dn > 0.f;
        g_rden[t*Nn + n] = ok ? 1.f/dn : 0.f;
        bad |= !ok;
    }
    if (bad) {
        int p = atomicAdd(&g_defCount, 1);
        g_defList[p] = n;
    }
}

// ---------------- packed f32x2 helpers ----------------
__device__ __forceinline__ u64 packf2(float lo, float hi) {
    u64 r;
    asm("mov.b64 %0, {%1, %2};" : "=l"(r) : "f"(lo), "f"(hi));
    return r;
}
__device__ __forceinline__ void unpackf2(u64 v, float& lo, float& hi) {
    asm("mov.b64 {%0, %1}, %2;" : "=f"(lo), "=f"(hi) : "l"(v));
}
__device__ __forceinline__ void fma2(u64& acc, u64 a, u64 b) {
    asm("fma.rn.f32x2 %0, %1, %2, %0;" : "+l"(acc) : "l"(a), "l"(b));
}

// ---------------- combine GEMM: out = relu([h | G0 | G1 | G2] @ Mbig + bu2) ----------------
// Tile 128 rows x 96 cols, K=384 in chunks of 32, thread tile 8x6, FFMA2 inner loop.
__global__ void __launch_bounds__(256) k_combine(const float* __restrict__ h,
                                                 float* __restrict__ out)
{
    __shared__ float As[32][132];   // transposed [k][row], padded
    __shared__ float Bs[32][96];
    __shared__ float Ss[3][128];
    int tid = threadIdx.x;
    int row0 = blockIdx.x * 128;

    for (int i = tid; i < 3*128; i += 256) {
        int t = i >> 7, r = i & 127;
        int n = row0 + r;
        Ss[t][r] = (n < Nn) ? g_rden[t*Nn + n] : 0.f;
    }
    __syncthreads();

    // acc2[ip][j] holds rows (rowg*8 + 2*ip, +2*ip+1) packed as f32x2
    u64 acc2[4][6];
    const u64 zz = 0ull;
    #pragma unroll
    for (int i = 0; i < 4; i++)
        #pragma unroll
        for (int j = 0; j < 6; j++) acc2[i][j] = zz;

    int rowg = tid >> 4, colg = tid & 15;

    for (int kc = 0; kc < 12; kc++) {
        int seg = kc / 3;            // 0: h, 1..3: agg_t
        int kin = (kc % 3) * 32;
        const float* Asrc = (seg == 0) ? h : (g_accum + (size_t)(seg - 1)*Nn*Hh);
        #pragma unroll
        for (int p = 0; p < 4; p++) {
            int r = (tid >> 3) + 32*p;
            int c4 = tid & 7;
            int n = row0 + r;
            float4 v = make_float4(0.f, 0.f, 0.f, 0.f);
            if (n < Nn) v = *reinterpret_cast<const float4*>(Asrc + (size_t)n*Hh + kin + c4*4);
            float sc = (seg == 0) ? 1.f : Ss[seg-1][r];
            As[c4*4+0][r] = v.x*sc;
            As[c4*4+1][r] = v.y*sc;
            As[c4*4+2][r] = v.z*sc;
            As[c4*4+3][r] = v.w*sc;
        }
        #pragma unroll
        for (int p = 0; p < 3; p++) {
            int i4 = tid + p*256;          // 0..767
            int kk = i4 / 24, j4 = i4 % 24;
            *reinterpret_cast<float4*>(&Bs[kk][j4*4]) =
                *reinterpret_cast<const float4*>(g_Mbig + (seg*96 + kin + kk)*96 + j4*4);
        }
        __syncthreads();
        #pragma unroll
        for (int k = 0; k < 32; k++) {
            float4 a0 = *reinterpret_cast<const float4*>(&As[k][rowg*8]);
            float4 a1 = *reinterpret_cast<const float4*>(&As[k][rowg*8+4]);
            float2 b0 = *reinterpret_cast<const float2*>(&Bs[k][colg*6]);
            float2 b1 = *reinterpret_cast<const float2*>(&Bs[k][colg*6+2]);
            float2 b2 = *reinterpret_cast<const float2*>(&Bs[k][colg*6+4]);
            u64 ap[4];
            ap[0] = packf2(a0.x, a0.y);
            ap[1] = packf2(a0.z, a0.w);
            ap[2] = packf2(a1.x, a1.y);
            ap[3] = packf2(a1.z, a1.w);
            u64 bd[6];
            bd[0] = packf2(b0.x, b0.x);
            bd[1] = packf2(b0.y, b0.y);
            bd[2] = packf2(b1.x, b1.x);
            bd[3] = packf2(b1.y, b1.y);
            bd[4] = packf2(b2.x, b2.x);
            bd[5] = packf2(b2.y, b2.y);
            #pragma unroll
            for (int ip = 0; ip < 4; ip++)
                #pragma unroll
                for (int j = 0; j < 6; j++)
                    fma2(acc2[ip][j], ap[ip], bd[j]);
        }
        __syncthreads();
    }

    #pragma unroll
    for (int ip = 0; ip < 4; ip++) {
        int n0 = row0 + rowg*8 + 2*ip;
        #pragma unroll
        for (int j = 0; j < 6; j++) {
            int c = colg*6 + j;
            float lo, hi;
            unpackf2(acc2[ip][j], lo, hi);
            float bias = g_bu2[c];
            if (n0 < Nn)     out[(size_t)n0*Hh + c]     = fmaxf(lo + bias, 0.f);
            if (n0 + 1 < Nn) out[(size_t)(n0+1)*Hh + c] = fmaxf(hi + bias, 0.f);
        }
    }
}

// ---------------- fixup for nodes with a zero-degree edge type ----------------
__global__ void k_fixup(const float* __restrict__ h, const float* __restrict__ bu,
                        float* __restrict__ out)
{
    int cnt = g_defCount;
    int j = threadIdx.x;   // 96 threads
    for (int i = blockIdx.x; i < cnt; i += gridDim.x) {
        int n = g_defList[i];
        float ok[3];
        #pragma unroll
        for (int t = 0; t < 3; t++)
            ok[t] = (g_accum[3*Nn*Hh + t*Nn + n] > 0.f) ? 1.f : 0.f;
        float y = bu[j];
        #pragma unroll
        for (int t = 0; t < 3; t++) y += ok[t]*g_cw[t][j];
        const float* hn = h + (size_t)n*Hh;
        for (int kk = 0; kk < Hh; kk++) {
            float m = g_Mbig[kk*Hh + j];
            #pragma unroll
            for (int t = 0; t < 3; t++)
                if (ok[t] == 0.f) m -= g_D[t][kk*Hh + j];
            y += hn[kk]*m;
        }
        #pragma unroll
        for (int t = 0; t < 3; t++) {
            if (ok[t] != 0.f) {
                float rd = g_rden[t*Nn + n];
                const float* agg = g_accum + (size_t)t*Nn*Hh + (size_t)n*Hh;
                for (int kk = 0; kk < Hh; kk++)
                    y += agg[kk]*rd*g_Mbig[(Hh + t*Hh + kk)*Hh + j];
            }
        }
        out[(size_t)n*Hh + j] = fmaxf(y, 0.f);
    }
}

// ---------------- launch ----------------
extern "C" void kernel_launch(void* const* d_in, const int* in_sizes, int n_in,
                              void* d_out, int out_size)
{
    const float* h    = (const float*)d_in[0];
    const int*   src0 = (const int*)d_in[1];
    const int*   dst0 = (const int*)d_in[2];
    const int*   src1 = (const int*)d_in[3];
    const int*   dst1 = (const int*)d_in[4];
    const int*   src2 = (const int*)d_in[5];
    const int*   dst2 = (const int*)d_in[6];
    const float* Wm0 = (const float*)d_in[7];
    const float* bm0 = (const float*)d_in[8];
    const float* ef0 = (const float*)d_in[9];
    const float* Wm1 = (const float*)d_in[10];
    const float* bm1 = (const float*)d_in[11];
    const float* ef1 = (const float*)d_in[12];
    const float* Wm2 = (const float*)d_in[13];
    const float* bm2 = (const float*)d_in[14];
    const float* ef2 = (const float*)d_in[15];
    const float* Wn0 = (const float*)d_in[16];
    const float* Wa0 = (const float*)d_in[17];
    const float* Wn1 = (const float*)d_in[18];
    const float* Wa1 = (const float*)d_in[19];
    const float* Wu  = (const float*)d_in[20];
    const float* bu  = (const float*)d_in[21];
    float* out = (float*)d_out;

    int E0 = in_sizes[1], E1 = in_sizes[3], E2 = in_sizes[5];

    // k_anode: 4 nodes/warp -> need ceil(Nn/4) warps
    int anode_blocks = ((Nn + 3)/4*32 + 255)/256;
    // merged edge kernel: total warps across 3 types
    int Wtot = (E0 + 3)/4 + (E1 + 3)/4 + (E2 + 3)/4;
    int edge_blocks = (Wtot*32 + 255)/256;

    k_zero<<<2048, 256>>>();
    k_prep_small<<<1, 96>>>(Wn0, Wa0, Wn1, Wa1,
                            Wm0, bm0, ef0, Wm1, bm1, ef1, Wm2, bm2, ef2, Wu, bu);
    k_prep_mats<<<(3*96*96 + 255)/256, 256>>>(Wm0, Wm1, Wm2, Wu);
    k_prep_m0<<<(96*96 + 255)/256, 256>>>(Wu);
    k_anode<<<anode_blocks, 256>>>(h);
    k_edge_all<<<edge_blocks, 256>>>(src0, dst0, src1, dst1, src2, dst2, h, E0, E1, E2);
    k_scan<<<(Nn + 255)/256, 256>>>();
    k_combine<<<(Nn + 127)/128, 256>>>(h, out);
    k_fixup<<<1024, 96>>>(h, bu, out);
}